// round 15
// baseline (speedup 1.0000x reference)
#include <cuda_runtime.h>
#include <cuda_fp16.h>

// SampleDepthwise deformable depthwise conv — fp16 quad table + HFMA2 blend,
// fp16 x staging, byte-packed quad indices, SINGLE-SYNC row pipeline:
// 4-slot x ring + double-buffered {coef, qidx, out} so load_xrow(r+2),
// precompute(r+1), store_out(r-1) and compute(r) share one barrier per row.
// B=8, C=256, H=W=96, K=3, S=4, PAD=1.

#define BN 8
#define CN 256
#define HN 96
#define WN 96
#define HW (HN * WN)

constexpr int CPB   = 64;          // channels per block
constexpr int NPAIR = CPB / 2;     // 32 channel pairs (one per lane)
constexpr int WPB   = 32;          // pixel columns per block
constexpr int RPB   = 16;          // rows per block -> 576 blocks
constexpr int NTH   = 256;         // 8 warps, 4 px each
constexpr int XW    = WPB + 2;     // 34 staged x columns
constexpr int XCH   = NPAIR + 1;   // 33 half2 per column (odd stride)
constexpr int SOH   = NPAIR + 1;   // 33 float2 per out row
constexpr int NQ    = 25;          // quads: y0 in [-1,3] x x0 in [-1,3]

// dynamic smem layout (bytes, all 16B aligned)
constexpr int SX_SLOT  = XW * XCH;                    // half2 per slot (1122)
constexpr int OFF_SQ   = 0;                           // uint4 [NQ*NPAIR]   12800
constexpr int OFF_SX   = 12800;                       // half2 [4][SX_SLOT] 17952
constexpr int OFF_SCF  = OFF_SX  + 4 * SX_SLOT * 4;   // uint2 [2][9*WPB]    4608
constexpr int OFF_SQB  = OFF_SCF + 2 * 9 * WPB * 8;   // uint4 [2][WPB]      1024
constexpr int OFF_SO   = OFF_SQB + 2 * WPB * 16;      // float2[2][WPB*SOH] 16896
constexpr int SMEM_TOTAL = OFF_SO + 2 * WPB * SOH * 8; // 53280

static __device__ __forceinline__ half2 u2h(unsigned int u) {
    half2 h;
    *reinterpret_cast<unsigned int*>(&h) = u;
    return h;
}
static __device__ __forceinline__ unsigned int h2u(half2 h) {
    return *reinterpret_cast<unsigned int*>(&h);
}

__global__ __launch_bounds__(NTH, 4)
void sdw_kernel(const float* __restrict__ x,
                const float* __restrict__ rot,
                const float* __restrict__ wgt,
                float* __restrict__ out)
{
    extern __shared__ __align__(16) char smem[];
    uint4*  sq  = reinterpret_cast<uint4*>(smem + OFF_SQ);
    half2*  sxh = reinterpret_cast<half2*>(smem + OFF_SX);
    uint2*  scf = reinterpret_cast<uint2*>(smem + OFF_SCF);
    uint4*  sqb = reinterpret_cast<uint4*>(smem + OFF_SQB);
    float2* so2 = reinterpret_cast<float2*>(smem + OFF_SO);

    const int tid  = threadIdx.x;
    const int lane = tid & 31;
    const int warp = tid >> 5;

    const int b     = blockIdx.y;
    const int c0    = blockIdx.z * CPB;
    const int wbase = (blockIdx.x % 3) * WPB;
    const int r0    = (blockIdx.x / 3) * RPB;

    // ---- fp16 quad table: sq[q][pair] = {h2(w00a,w00b), ..., h2(w11a,w11b)} ----
    for (int i = tid; i < NQ * NPAIR; i += NTH) {
        const int q  = i / NPAIR;
        const int p  = i % NPAIR;
        const int y0 = q / 5 - 1;
        const int x0 = q % 5 - 1;
        const float* wa = wgt + (c0 + 2 * p) * 16;
        const float* wb = wa + 16;
        auto corner = [&](const float* wc, int y, int xq) -> float {
            return (y >= 0 && y < 4 && xq >= 0 && xq < 4) ? __ldg(wc + y * 4 + xq) : 0.f;
        };
        uint4 u;
        u.x = h2u(__floats2half2_rn(corner(wa, y0,     x0    ), corner(wb, y0,     x0    )));
        u.y = h2u(__floats2half2_rn(corner(wa, y0,     x0 + 1), corner(wb, y0,     x0 + 1)));
        u.z = h2u(__floats2half2_rn(corner(wa, y0 + 1, x0    ), corner(wb, y0 + 1, x0    )));
        u.w = h2u(__floats2half2_rn(corner(wa, y0 + 1, x0 + 1), corner(wb, y0 + 1, x0 + 1)));
        sq[i] = u;
    }

    // ---- x row staging: slot(r) = (r+1) & 3 ----
    auto load_xrow = [&](int r) {
        half2* dst = sxh + ((r + 1) & 3) * SX_SLOT;
        const bool rvalid = (unsigned)r < (unsigned)HN;
        const int  rr = rvalid ? r : 0;
        const float* src = x + (((size_t)b * CN + c0) * HN + rr) * WN + wbase;
        const int w_ = tid & 31;
        const int pb = tid >> 5;
        #pragma unroll
        for (int k = 0; k < 4; k++) {
            const int p = pb + k * 8;                       // pair 0..31
            float v0 = 0.f, v1 = 0.f;
            if (rvalid) {
                v0 = __ldg(src + (size_t)(2 * p)     * HW + w_);
                v1 = __ldg(src + (size_t)(2 * p + 1) * HW + w_);
            }
            dst[(1 + w_) * XCH + p] = __floats2half2_rn(v0, v1);
        }
        // halo columns 0 and 33
        if (tid < 64) {
            const int p    = tid >> 1;
            const int side = tid & 1;
            const int wq   = side ? 33 : 0;
            const int gw   = wbase + wq - 1;
            float v0 = 0.f, v1 = 0.f;
            if (rvalid && (unsigned)gw < (unsigned)WN) {
                const float* hp = x + (((size_t)b * CN + c0 + 2 * p) * HN + rr) * WN + gw;
                v0 = __ldg(hp);
                v1 = __ldg(hp + HW);
            }
            dst[wq * XCH + p] = __floats2half2_rn(v0, v1);
        }
    };

    constexpr float B0 = (float)(0.5 * 4.0 / 3.0 - 0.5);
    constexpr float B1 = (float)(1.5 * 4.0 / 3.0 - 0.5);
    constexpr float B2 = (float)(2.5 * 4.0 / 3.0 - 0.5);

    auto precompute = [&](int r) {
        const int buf = r & 1;
        uint2* scb = scf + buf * (9 * WPB);
        unsigned char* qbb = reinterpret_cast<unsigned char*>(sqb + buf * WPB);
        for (int t = tid; t < 9 * WPB; t += NTH) {
            const int tap = t >> 5;
            const int px  = t & 31;
            const int kh = tap / 3, kw = tap % 3;
            const float* rp = rot + (((size_t)b * 18 + 2 * tap) * HN + r) * WN + wbase + px;
            const float ry = __ldg(rp);
            const float rx = __ldg(rp + HW);
            const float yb = (kh == 0) ? B0 : ((kh == 1) ? B1 : B2);
            const float xb = (kw == 0) ? B0 : ((kw == 1) ? B1 : B2);
            const float py = yb + ry, pxx = xb + rx;
            const float y0f = floorf(py), x0f = floorf(pxx);
            const float fy = py - y0f, fx = pxx - x0f;
            const bool vy0 = (y0f >=  0.f) && (y0f <= 3.f);
            const bool vy1 = (y0f >= -1.f) && (y0f <= 2.f);
            const bool vx0 = (x0f >=  0.f) && (x0f <= 3.f);
            const bool vx1 = (x0f >= -1.f) && (x0f <= 2.f);
            const float gy0 = 1.f - fy, gy1 = fy;
            const float gx0 = 1.f - fx, gx1 = fx;
            const float c00 = (vy0 && vx0) ? gy0 * gx0 : 0.f;
            const float c01 = (vy0 && vx1) ? gy0 * gx1 : 0.f;
            const float c10 = (vy1 && vx0) ? gy1 * gx0 : 0.f;
            const float c11 = (vy1 && vx1) ? gy1 * gx1 : 0.f;
            const int qy = (int)fminf(fmaxf(y0f, -1.f), 3.f) + 1;
            const int qx = (int)fminf(fmaxf(x0f, -1.f), 3.f) + 1;
            uint2 pc;
            pc.x = h2u(__floats2half2_rn(c00, c01));
            pc.y = h2u(__floats2half2_rn(c10, c11));
            scb[t] = pc;
            qbb[px * 16 + tap] = (unsigned char)(qy * 5 + qx);
        }
    };

    auto store_out = [&](int rr) {
        const float2* sob = so2 + (rr & 1) * (WPB * SOH);
        const int w = tid & 31;
        #pragma unroll
        for (int it = 0; it < 4; it++) {
            const int p = (tid >> 5) + it * 8;              // pair 0..31
            const float2 v = sob[w * SOH + p];
            float* op = out + (((size_t)b * CN + c0 + 2 * p) * HN + rr) * WN + wbase + w;
            op[0]  = v.x;
            op[HW] = v.y;
        }
    };

    // ---- prologue: 3 rows staged, coefs for r0 ----
    load_xrow(r0 - 1);
    load_xrow(r0);
    load_xrow(r0 + 1);
    precompute(r0);
    __syncthreads();

    const char* sqc = reinterpret_cast<const char*>(sq) + lane * 16;
    const int p0 = warp * 4;

    for (int r = r0; r < r0 + RPB; r++) {
        // concurrent staging for neighboring rows (disjoint buffers/slots)
        if (r + 2 <= r0 + RPB) load_xrow(r + 2);
        if (r + 1 <  r0 + RPB) precompute(r + 1);
        if (r > r0)            store_out(r - 1);

        // compute row r
        const int buf = r & 1;
        const uint2* cfb = scf + buf * (9 * WPB);
        const uint4* qbp = sqb + buf * WPB;
        float2* sob = so2 + buf * (WPB * SOH);

        const half2* row_m1 = sxh + ( r      & 3) * SX_SLOT + lane;
        const half2* row_0  = sxh + ((r + 1) & 3) * SX_SLOT + lane;
        const half2* row_p1 = sxh + ((r + 2) & 3) * SX_SLOT + lane;

        uint4 qb[4];
        #pragma unroll
        for (int pp = 0; pp < 4; pp++) qb[pp] = qbp[p0 + pp];   // uniform broadcast

        float2 acc[4];
        #pragma unroll
        for (int pp = 0; pp < 4; pp++) acc[pp] = make_float2(0.f, 0.f);

        #pragma unroll
        for (int kh = 0; kh < 3; kh++) {
            const half2* xr = (kh == 0) ? row_m1 : ((kh == 1) ? row_0 : row_p1);
            float2 xv[6];
            #pragma unroll
            for (int j = 0; j < 6; j++)
                xv[j] = __half22float2(xr[(p0 + j) * XCH]);

            #pragma unroll
            for (int kw = 0; kw < 3; kw++) {
                const int tap = kh * 3 + kw;
                const uint2* cfp = cfb + tap * WPB + p0;
                #pragma unroll
                for (int pp = 0; pp < 4; pp++) {
                    const unsigned wsel = (tap < 4) ? qb[pp].x
                                        : (tap < 8) ? qb[pp].y : qb[pp].z;
                    const unsigned qo = ((wsel >> ((tap & 3) * 8)) & 0xFFu) * (NPAIR * 16);
                    const uint4 qv = *reinterpret_cast<const uint4*>(sqc + qo);
                    const uint2 cf = cfp[pp];                       // uniform LDS.64
                    const half2 cl  = u2h(cf.x);                    // (c00, c01)
                    const half2 chh = u2h(cf.y);                    // (c10, c11)
                    half2 g2 = __hmul2(__low2half2(cl),  u2h(qv.x));
                    g2 = __hfma2(__high2half2(cl),  u2h(qv.y), g2);
                    g2 = __hfma2(__low2half2(chh),  u2h(qv.z), g2);
                    g2 = __hfma2(__high2half2(chh), u2h(qv.w), g2);
                    const float2 g  = __half22float2(g2);
                    const float2 xx = xv[pp + kw];
                    acc[pp].x = fmaf(g.x, xx.x, acc[pp].x);
                    acc[pp].y = fmaf(g.y, xx.y, acc[pp].y);
                }
            }
        }

        #pragma unroll
        for (int pp = 0; pp < 4; pp++)
            sob[(p0 + pp) * SOH + lane] = acc[pp];
        __syncthreads();
    }
    store_out(r0 + RPB - 1);
}

extern "C" void kernel_launch(void* const* d_in, const int* in_sizes, int n_in,
                              void* d_out, int out_size)
{
    const float* x   = (const float*)d_in[0];
    const float* rot = (const float*)d_in[1];
    const float* wgt = (const float*)d_in[2];
    float* out = (float*)d_out;

    cudaFuncSetAttribute(sdw_kernel, cudaFuncAttributeMaxDynamicSharedMemorySize, SMEM_TOTAL);

    dim3 block(NTH, 1, 1);
    dim3 grid(3 * (HN / RPB), BN, CN / CPB);   // 18 x 8 x 4 = 576 blocks
    sdw_kernel<<<grid, block, SMEM_TOTAL>>>(x, rot, wgt, out);
}

// round 17
// speedup vs baseline: 1.0976x; 1.0976x over previous
#include <cuda_runtime.h>
#include <cuda_fp16.h>

// SampleDepthwise deformable depthwise conv — fp16 quad table + full-HFMA2
// datapath: blend AND accumulate in half2; x stays half2 end-to-end; one
// half2->float2 conversion per output pair. Byte-packed quad indices.
// Structure = proven two-sync row loop (103.1 us base). 4 blocks/SM.
// B=8, C=256, H=W=96, K=3, S=4, PAD=1.

#define BN 8
#define CN 256
#define HN 96
#define WN 96
#define HW (HN * WN)

constexpr int CPB   = 64;          // channels per block
constexpr int NPAIR = CPB / 2;     // 32 channel pairs (one per lane)
constexpr int WPB   = 32;          // pixel columns per block
constexpr int RPB   = 16;          // rows per block -> 576 blocks
constexpr int NTH   = 256;         // 8 warps, 4 px each
constexpr int XW    = WPB + 2;     // 34 staged x columns
constexpr int XCH   = NPAIR + 1;   // 33 half2 per column (odd stride, conflict-free)
constexpr int SOH   = NPAIR + 1;   // 33 float2 per out row
constexpr int NQ    = 25;          // quads: y0 in [-1,3] x x0 in [-1,3]

static __device__ __forceinline__ half2 u2h(unsigned int u) {
    half2 h;
    *reinterpret_cast<unsigned int*>(&h) = u;
    return h;
}
static __device__ __forceinline__ unsigned int h2u(half2 h) {
    return *reinterpret_cast<unsigned int*>(&h);
}

__global__ __launch_bounds__(NTH, 4)
void sdw_kernel(const float* __restrict__ x,
                const float* __restrict__ rot,
                const float* __restrict__ wgt,
                float* __restrict__ out)
{
    __shared__ __align__(16) uint4  sq[NQ * NPAIR];     // 12800 B fp16 quad table
    __shared__ __align__(16) half2  sxh[3 * XW * XCH];  // 13464 B x ring
    __shared__ __align__(16) uint2  scf[9 * WPB];       //  2304 B coefs (2x half2)
    __shared__ __align__(16) uint4  sqb[WPB];           //   512 B 9 qidx bytes per px
    __shared__ __align__(16) float2 so2[WPB * SOH];     //  8448 B out staging

    const int tid  = threadIdx.x;
    const int lane = tid & 31;
    const int warp = tid >> 5;

    const int b     = blockIdx.y;
    const int c0    = blockIdx.z * CPB;
    const int wbase = (blockIdx.x % 3) * WPB;
    const int r0    = (blockIdx.x / 3) * RPB;

    // ---- fp16 quad table: sq[q][pair] = {h2(w00a,w00b), ..., h2(w11a,w11b)} ----
    for (int i = tid; i < NQ * NPAIR; i += NTH) {
        const int q  = i / NPAIR;
        const int p  = i % NPAIR;
        const int y0 = q / 5 - 1;
        const int x0 = q % 5 - 1;
        const float* wa = wgt + (c0 + 2 * p) * 16;
        const float* wb = wa + 16;
        auto corner = [&](const float* wc, int y, int xq) -> float {
            return (y >= 0 && y < 4 && xq >= 0 && xq < 4) ? __ldg(wc + y * 4 + xq) : 0.f;
        };
        uint4 u;
        u.x = h2u(__floats2half2_rn(corner(wa, y0,     x0    ), corner(wb, y0,     x0    )));
        u.y = h2u(__floats2half2_rn(corner(wa, y0,     x0 + 1), corner(wb, y0,     x0 + 1)));
        u.z = h2u(__floats2half2_rn(corner(wa, y0 + 1, x0    ), corner(wb, y0 + 1, x0    )));
        u.w = h2u(__floats2half2_rn(corner(wa, y0 + 1, x0 + 1), corner(wb, y0 + 1, x0 + 1)));
        sq[i] = u;
    }

    // ---- x row staging: gmem fp32 -> smem half2 channel pairs ----
    auto load_xrow = [&](int r) {
        half2* dst = sxh + ((r + 1) % 3) * (XW * XCH);
        const bool rvalid = (unsigned)r < (unsigned)HN;
        const int  rr = rvalid ? r : 0;
        const float* src = x + (((size_t)b * CN + c0) * HN + rr) * WN + wbase;
        const int w_ = tid & 31;
        const int pb = tid >> 5;
        #pragma unroll
        for (int k = 0; k < 4; k++) {
            const int p = pb + k * 8;                       // pair 0..31
            float v0 = 0.f, v1 = 0.f;
            if (rvalid) {
                v0 = __ldg(src + (size_t)(2 * p)     * HW + w_);
                v1 = __ldg(src + (size_t)(2 * p + 1) * HW + w_);
            }
            dst[(1 + w_) * XCH + p] = __floats2half2_rn(v0, v1);
        }
        // halo columns 0 and 33
        if (tid < 64) {
            const int p    = tid >> 1;
            const int side = tid & 1;
            const int wq   = side ? 33 : 0;
            const int gw   = wbase + wq - 1;
            float v0 = 0.f, v1 = 0.f;
            if (rvalid && (unsigned)gw < (unsigned)WN) {
                const float* hp = x + (((size_t)b * CN + c0 + 2 * p) * HN + rr) * WN + gw;
                v0 = __ldg(hp);
                v1 = __ldg(hp + HW);
            }
            dst[wq * XCH + p] = __floats2half2_rn(v0, v1);
        }
    };

    constexpr float B0 = (float)(0.5 * 4.0 / 3.0 - 0.5);
    constexpr float B1 = (float)(1.5 * 4.0 / 3.0 - 0.5);
    constexpr float B2 = (float)(2.5 * 4.0 / 3.0 - 0.5);

    auto precompute = [&](int r) {
        for (int t = tid; t < 9 * WPB; t += NTH) {
            const int tap = t >> 5;
            const int px  = t & 31;
            const int kh = tap / 3, kw = tap % 3;
            const float* rp = rot + (((size_t)b * 18 + 2 * tap) * HN + r) * WN + wbase + px;
            const float ry = __ldg(rp);
            const float rx = __ldg(rp + HW);
            const float yb = (kh == 0) ? B0 : ((kh == 1) ? B1 : B2);
            const float xb = (kw == 0) ? B0 : ((kw == 1) ? B1 : B2);
            const float py = yb + ry, pxx = xb + rx;
            const float y0f = floorf(py), x0f = floorf(pxx);
            const float fy = py - y0f, fx = pxx - x0f;
            const bool vy0 = (y0f >=  0.f) && (y0f <= 3.f);
            const bool vy1 = (y0f >= -1.f) && (y0f <= 2.f);
            const bool vx0 = (x0f >=  0.f) && (x0f <= 3.f);
            const bool vx1 = (x0f >= -1.f) && (x0f <= 2.f);
            const float gy0 = 1.f - fy, gy1 = fy;
            const float gx0 = 1.f - fx, gx1 = fx;
            const float c00 = (vy0 && vx0) ? gy0 * gx0 : 0.f;
            const float c01 = (vy0 && vx1) ? gy0 * gx1 : 0.f;
            const float c10 = (vy1 && vx0) ? gy1 * gx0 : 0.f;
            const float c11 = (vy1 && vx1) ? gy1 * gx1 : 0.f;
            const int qy = (int)fminf(fmaxf(y0f, -1.f), 3.f) + 1;
            const int qx = (int)fminf(fmaxf(x0f, -1.f), 3.f) + 1;
            uint2 pc;
            pc.x = h2u(__floats2half2_rn(c00, c01));
            pc.y = h2u(__floats2half2_rn(c10, c11));
            scf[t] = pc;
            // byte-store the quad index (0..24) into sqb[px] byte 'tap'
            reinterpret_cast<unsigned char*>(sqb)[px * 16 + tap] =
                (unsigned char)(qy * 5 + qx);
        }
    };

    auto store_out = [&](int rr) {
        const int w = tid & 31;
        #pragma unroll
        for (int it = 0; it < 4; it++) {
            const int p = (tid >> 5) + it * 8;              // pair 0..31
            const float2 v = so2[w * SOH + p];
            float* op = out + (((size_t)b * CN + c0 + 2 * p) * HN + rr) * WN + wbase + w;
            op[0]  = v.x;
            op[HW] = v.y;
        }
    };

    // ---- prologue ----
    load_xrow(r0 - 1);
    load_xrow(r0);

    const char* sqc = reinterpret_cast<const char*>(sq) + lane * 16;
    const int p0 = warp * 4;

    for (int r = r0; r < r0 + RPB; r++) {
        load_xrow(r + 1);
        precompute(r);
        if (r > r0) store_out(r - 1);
        __syncthreads();

        const half2* row_m1 = sxh + ( r      % 3) * (XW * XCH) + lane;
        const half2* row_0  = sxh + ((r + 1) % 3) * (XW * XCH) + lane;
        const half2* row_p1 = sxh + ((r + 2) % 3) * (XW * XCH) + lane;

        // all 9 quad indices per pixel, loaded once (independent of coef loads)
        uint4 qb[4];
        #pragma unroll
        for (int pp = 0; pp < 4; pp++) qb[pp] = sqb[p0 + pp];   // uniform broadcast

        half2 acc[4];
        #pragma unroll
        for (int pp = 0; pp < 4; pp++) acc[pp] = u2h(0u);

        #pragma unroll
        for (int kh = 0; kh < 3; kh++) {
            const half2* xr = (kh == 0) ? row_m1 : ((kh == 1) ? row_0 : row_p1);
            half2 xv[6];
            #pragma unroll
            for (int j = 0; j < 6; j++)
                xv[j] = xr[(p0 + j) * XCH];                 // raw half2, no cvt

            #pragma unroll
            for (int kw = 0; kw < 3; kw++) {
                const int tap = kh * 3 + kw;
                const uint2* cfp = scf + tap * WPB + p0;
                #pragma unroll
                for (int pp = 0; pp < 4; pp++) {
                    // static byte extraction of quad index (tap is compile-time)
                    const unsigned wsel = (tap < 4) ? qb[pp].x
                                        : (tap < 8) ? qb[pp].y : qb[pp].z;
                    const unsigned qo = ((wsel >> ((tap & 3) * 8)) & 0xFFu) * (NPAIR * 16);
                    const uint4 qv = *reinterpret_cast<const uint4*>(sqc + qo);
                    const uint2 cf = cfp[pp];                       // uniform LDS.64
                    const half2 cl  = u2h(cf.x);                    // (c00, c01)
                    const half2 chh = u2h(cf.y);                    // (c10, c11)
                    half2 g2 = __hmul2(__low2half2(cl),  u2h(qv.x));
                    g2 = __hfma2(__high2half2(cl),  u2h(qv.y), g2);
                    g2 = __hfma2(__low2half2(chh),  u2h(qv.z), g2);
                    g2 = __hfma2(__high2half2(chh), u2h(qv.w), g2);
                    acc[pp] = __hfma2(g2, xv[pp + kw], acc[pp]);    // half2 accumulate
                }
            }
        }

        #pragma unroll
        for (int pp = 0; pp < 4; pp++)
            so2[(p0 + pp) * SOH + lane] = __half22float2(acc[pp]);
        __syncthreads();
    }
    store_out(r0 + RPB - 1);
}

extern "C" void kernel_launch(void* const* d_in, const int* in_sizes, int n_in,
                              void* d_out, int out_size)
{
    const float* x   = (const float*)d_in[0];
    const float* rot = (const float*)d_in[1];
    const float* wgt = (const float*)d_in[2];
    float* out = (float*)d_out;

    dim3 block(NTH, 1, 1);
    dim3 grid(3 * (HN / RPB), BN, CN / CPB);   // 18 x 8 x 4 = 576 blocks
    sdw_kernel<<<grid, block>>>(x, rot, wgt, out);
}